// round 5
// baseline (speedup 1.0000x reference)
#include <cuda_runtime.h>
#include <cuda_fp16.h>
#include <stdint.h>

// Problem constants
#define Q_I     512
#define Q_O     32
#define Q_JD    8                  // dense degree slots per input (j=1..8; j=0 folded to bias)
#define Q_CHI   16                 // inputs per chunk
#define Q_CHK   128                // k per chunk (16*8), 8 k16-steps
#define Q_NCH   32                 // 512/16
#define Q_ROWS  128                // batch rows per CTA
#define Q_THR   128                // 4 warps

// smem (halves): W [32][136] then basisT [128][136]
#define WPAD    136
#define BPAD    136
#define SM_W    0
#define SM_B    (Q_O * WPAD * 2)                  // 8704 bytes
#define SM_TOT  (SM_B + Q_CHK * BPAD * 2)         // 43520 bytes

// Repacked fp16 weights (dense j=1..8): g_W2[c][o][kl], kl = ip*8 + (j-1)
__device__ __half g_W2[Q_NCH * Q_O * Q_CHK];
__device__ float  g_bias[Q_O];

__global__ void repack_kernel(const float* __restrict__ w) {
    int idx = blockIdx.x * blockDim.x + threadIdx.x;
    if (idx >= Q_NCH * Q_O * Q_CHK) return;
    int kl = idx & 127;
    int o  = (idx >> 7) & 31;
    int c  = idx >> 12;
    int i  = c * Q_CHI + (kl >> 3);
    int j  = (kl & 7) + 1;
    g_W2[idx] = __float2half(w[(i * Q_O + o) * 9 + j]);
}

__global__ void bias_kernel(const float* __restrict__ w) {
    int o = threadIdx.x;              // 32 threads
    float s = 0.0f;
    for (int i = 0; i < Q_I; ++i) s += w[(i * Q_O + o) * 9];
    g_bias[o] = s;
}

// ---------------- primitives ----------------
__device__ __forceinline__ uint32_t smem_u32(const void* p) {
    uint32_t a;
    asm("{ .reg .u64 t; cvta.to.shared.u64 t, %1; cvt.u32.u64 %0, t; }" : "=r"(a) : "l"(p));
    return a;
}
__device__ __forceinline__ void ldm_x4(uint32_t (&r)[4], uint32_t addr) {
    asm volatile("ldmatrix.sync.aligned.m8n8.x4.shared.b16 {%0,%1,%2,%3}, [%4];"
                 : "=r"(r[0]), "=r"(r[1]), "=r"(r[2]), "=r"(r[3]) : "r"(addr));
}
__device__ __forceinline__ void ldm_x4_t(uint32_t (&r)[4], uint32_t addr) {
    asm volatile("ldmatrix.sync.aligned.m8n8.x4.trans.shared.b16 {%0,%1,%2,%3}, [%4];"
                 : "=r"(r[0]), "=r"(r[1]), "=r"(r[2]), "=r"(r[3]) : "r"(addr));
}
__device__ __forceinline__ void mma16816(float (&d)[4], const uint32_t (&a)[4],
                                         uint32_t b0, uint32_t b1) {
    asm volatile(
        "mma.sync.aligned.m16n8k16.row.col.f32.f16.f16.f32 "
        "{%0,%1,%2,%3}, {%4,%5,%6,%7}, {%8,%9}, {%0,%1,%2,%3};"
        : "+f"(d[0]), "+f"(d[1]), "+f"(d[2]), "+f"(d[3])
        : "r"(a[0]), "r"(a[1]), "r"(a[2]), "r"(a[3]), "r"(b0), "r"(b1));
}
__device__ __forceinline__ uint32_t pack2(float a, float b) {
    __half2 h = __floats2half2_rn(a, b);
    return *reinterpret_cast<uint32_t*>(&h);
}
// tanh(x) = 1 - 2/(exp2(2x*log2e)+1)  (~5 slots, rel err ~1e-6)
__device__ __forceinline__ float ftanh(float x) {
    float p;
    asm("ex2.approx.f32 %0, %1;" : "=f"(p) : "f"(x * 2.8853900817779268f));
    float r;
    asm("rcp.approx.f32 %0, %1;" : "=f"(r) : "f"(p + 1.0f));
    return fmaf(-2.0f, r, 1.0f);
}

__global__ __launch_bounds__(Q_THR, 5)
void cheby_mma_kernel(const float* __restrict__ x, float* __restrict__ out) {
    extern __shared__ char smem[];
    const uint32_t sW = smem_u32(smem) + SM_W;
    const uint32_t sB = smem_u32(smem) + SM_B;

    const int t    = threadIdx.x;
    const int lane = t & 31;
    const int w    = t >> 5;             // warp id; also gen input-group
    const int b0   = blockIdx.x * Q_ROWS;

    // gen mapping: thread owns rows 4*rq..4*rq+3, inputs ig*4..ig*4+3 of the chunk
    const int rq = lane;                 // 0..31 (warp-local lane)
    const int ig = w;                    // 0..3

    // ldmatrix lane address components
    const int g = lane >> 3, l = lane & 7;
    const int oRow = (g & 1) * 8 + l;
    const int kHlf = (g >> 1) * 8;
    const uint32_t wAddrBase = sW + (uint32_t)(oRow * WPAD + kHlf) * 2u;
    const int kOff = (g >> 1) * 8 + l;
    const int mOff = (g & 1) * 8;
    const uint32_t bAddrBase = sB + (uint32_t)(kOff * BPAD + w * 32 + mOff) * 2u;

    float acc[2][4][4];
#pragma unroll
    for (int ot = 0; ot < 2; ++ot)
#pragma unroll
        for (int rt = 0; rt < 4; ++rt)
#pragma unroll
            for (int q = 0; q < 4; ++q) acc[ot][rt][q] = 0.0f;

    // x base for this thread's 4 rows, this warp's 4 inputs
    const float* xbase = x + (size_t)(b0 + 4 * rq) * Q_I + ig * 4;

    // ---- prefetch chunk 0 ----
    float4 xp[4];
    uint4  wp[4];
#pragma unroll
    for (int r = 0; r < 4; ++r)
        xp[r] = *reinterpret_cast<const float4*>(xbase + (size_t)r * Q_I);
    {
        const __half* wg = g_W2;
#pragma unroll
        for (int q = 0; q < 4; ++q)
            wp[q] = *reinterpret_cast<const uint4*>(wg + (q * 128 + t) * 8);
    }

    for (int c = 0; c < Q_NCH; ++c) {
        if (c) __syncthreads();          // mma(c-1) finished reading smem

        // ---- stage W chunk: flat = q*128 + t -> o = flat/16, seg = flat%16 ----
#pragma unroll
        for (int q = 0; q < 4; ++q) {
            int flat = q * 128 + t;
            int o = flat >> 4, seg = flat & 15;
            asm volatile("st.shared.v4.b32 [%0], {%1,%2,%3,%4};"
                         :: "r"(sW + (uint32_t)(o * WPAD + seg * 8) * 2u),
                            "r"(wp[q].x), "r"(wp[q].y), "r"(wp[q].z), "r"(wp[q].w));
        }

        // ---- generate basis tile from xp ----
        {
            float xv[4][4];
#pragma unroll
            for (int r = 0; r < 4; ++r) {
                xv[r][0] = xp[r].x; xv[r][1] = xp[r].y;
                xv[r][2] = xp[r].z; xv[r][3] = xp[r].w;
            }
#pragma unroll
            for (int p = 0; p < 4; ++p) {
                float x2[4], up[4], uc[4];
#pragma unroll
                for (int r = 0; r < 4; ++r) {
                    float tt = ftanh(xv[r][p]);
                    x2[r] = tt + tt;
                    up[r] = 1.0f;
                    uc[r] = x2[r];
                }
                uint32_t ad = sB + (uint32_t)(((ig * 4 + p) * Q_JD) * (BPAD * 2)) + (uint32_t)(rq * 8);
#pragma unroll
                for (int j = 1; j <= 8; ++j) {
                    uint32_t h0 = pack2(uc[0], uc[1]);
                    uint32_t h1 = pack2(uc[2], uc[3]);
                    asm volatile("st.shared.v2.b32 [%0], {%1,%2};" :: "r"(ad), "r"(h0), "r"(h1));
                    ad += BPAD * 2;
                    if (j < 8) {
#pragma unroll
                        for (int r = 0; r < 4; ++r) {
                            float un = fmaf(x2[r], uc[r], -up[r]);
                            up[r] = uc[r]; uc[r] = un;
                        }
                    }
                }
            }
        }
        __syncthreads();

        // ---- prefetch chunk c+1 (LDG only; hidden under MMA) ----
        if (c + 1 < Q_NCH) {
#pragma unroll
            for (int r = 0; r < 4; ++r)
                xp[r] = *reinterpret_cast<const float4*>(xbase + (c + 1) * Q_CHI + (size_t)r * Q_I);
            const __half* wg = g_W2 + (size_t)(c + 1) * (Q_O * Q_CHK);
#pragma unroll
            for (int q = 0; q < 4; ++q)
                wp[q] = *reinterpret_cast<const uint4*>(wg + (q * 128 + t) * 8);
        }

        // ---- MMA: 8 k16-steps ----
        uint32_t wAddr = wAddrBase;
        uint32_t bAddr = bAddrBase;
#pragma unroll
        for (int ks = 0; ks < 8; ++ks) {
            uint32_t aW0[4], aW1[4], bb0[4], bb1[4];
            ldm_x4(aW0, wAddr);                       // o 0..15
            ldm_x4(aW1, wAddr + 16u * WPAD * 2u);     // o 16..31
            ldm_x4_t(bb0, bAddr);                     // rows m0..m0+15
            ldm_x4_t(bb1, bAddr + 32u);               // rows m0+16..m0+31
            mma16816(acc[0][0], aW0, bb0[0], bb0[2]);
            mma16816(acc[1][0], aW1, bb0[0], bb0[2]);
            mma16816(acc[0][1], aW0, bb0[1], bb0[3]);
            mma16816(acc[1][1], aW1, bb0[1], bb0[3]);
            mma16816(acc[0][2], aW0, bb1[0], bb1[2]);
            mma16816(acc[1][2], aW1, bb1[0], bb1[2]);
            mma16816(acc[0][3], aW0, bb1[1], bb1[3]);
            mma16816(acc[1][3], aW1, bb1[1], bb1[3]);
            wAddr += 32u;                 // +16 halves along k
            bAddr += 16u * BPAD * 2u;     // +16 k-rows
        }
    }

    // ---- epilogue: add bias, store ----
    const int qr = lane >> 2;
    const int qc = (lane & 3) * 2;
    float bo[2][2];
#pragma unroll
    for (int ot = 0; ot < 2; ++ot) {
        bo[ot][0] = g_bias[ot * 16 + qr];
        bo[ot][1] = g_bias[ot * 16 + qr + 8];
    }
#pragma unroll
    for (int rt = 0; rt < 4; ++rt) {
        int r = b0 + 32 * w + 8 * rt + qc;
        float* po0 = out + (size_t)r * Q_O;
        float* po1 = out + (size_t)(r + 1) * Q_O;
#pragma unroll
        for (int ot = 0; ot < 2; ++ot) {
            int o = ot * 16 + qr;
            po0[o]     = acc[ot][rt][0] + bo[ot][0];
            po1[o]     = acc[ot][rt][1] + bo[ot][0];
            po0[o + 8] = acc[ot][rt][2] + bo[ot][1];
            po1[o + 8] = acc[ot][rt][3] + bo[ot][1];
        }
    }
}

extern "C" void kernel_launch(void* const* d_in, const int* in_sizes, int n_in,
                              void* d_out, int out_size) {
    const float* x  = (const float*)d_in[0];     // [65536, 512] f32
    const float* wc = (const float*)d_in[1];     // [512, 32, 9] f32
    float* out = (float*)d_out;                  // [65536, 32] f32

    int Brows = in_sizes[0] / Q_I;

    int wtot = Q_NCH * Q_O * Q_CHK;              // 131072
    repack_kernel<<<(wtot + 255) / 256, 256>>>(wc);
    bias_kernel<<<1, Q_O>>>(wc);

    cheby_mma_kernel<<<Brows / Q_ROWS, Q_THR, SM_TOT>>>(x, out);
}